// round 5
// baseline (speedup 1.0000x reference)
#include <cuda_runtime.h>

// VQ layer forward == identity on inputs (verified rel_err 1.1e-8, gate 1e-3).
//
// R1-R4 post-mortem: four disjoint copy paths (LDG/STG, MLP-4, TMA bulk,
// copy-engine memcpy) ALL land at 6.6 +/- 0.1us with every counter idle.
// => each single path tops out at ~2.7 TB/s effective for this 16.8MB
// transfer (launch ramp + serial path). R5: split the copy across TWO
// concurrent hardware paths -- copy engine (SDMA) and SMs -- as parallel
// branches of the captured graph (fork/join via events). Each path moves
// 4 MiB; transfer term halves, ramp paid once in parallel.

__global__ void vq_copy_half(const float4* __restrict__ src,
                             float4* __restrict__ dst,
                             int n4) {
    int i = blockIdx.x * blockDim.x + threadIdx.x;
    if (i < n4) dst[i] = src[i];
}

extern "C" void kernel_launch(void* const* d_in, const int* in_sizes, int n_in,
                              void* d_out, int out_size) {
    const char* src = (const char*)d_in[0];
    char* dst = (char*)d_out;
    const size_t bytes = (size_t)out_size * sizeof(float);  // 8 MiB
    const size_t half = bytes / 2;                           // 4 MiB, 16B-aligned

    // Lazily created on the first (correctness) call, which happens BEFORE
    // graph capture; reused thereafter. No device memory is allocated.
    static cudaStream_t side = nullptr;
    static cudaEvent_t ev_fork = nullptr, ev_join = nullptr;
    if (side == nullptr) {
        cudaStreamCreateWithFlags(&side, cudaStreamNonBlocking);
        cudaEventCreateWithFlags(&ev_fork, cudaEventDisableTiming);
        cudaEventCreateWithFlags(&ev_join, cudaEventDisableTiming);
    }

    // Fork: side stream joins the capture of the main (default) stream.
    cudaEventRecord(ev_fork, 0);
    cudaStreamWaitEvent(side, ev_fork, 0);

    // Branch A (copy engine): first half, SDMA path.
    cudaMemcpyAsync(dst, src, half, cudaMemcpyDeviceToDevice, side);
    cudaEventRecord(ev_join, side);

    // Branch B (SMs): second half, R1-shaped LDG/STG copy (fastest SM variant).
    {
        int n4 = (int)(half / sizeof(float4));   // 262,144 float4
        const int threads = 256;
        int blocks = (n4 + threads - 1) / threads;  // 1024
        vq_copy_half<<<blocks, threads, 0, 0>>>(
            (const float4*)(src + half), (float4*)(dst + half), n4);
    }

    // Join: main stream waits for the CE branch.
    cudaStreamWaitEvent(0, ev_join, 0);
}

// round 6
// speedup vs baseline: 1.0463x; 1.0463x over previous
#include <cuda_runtime.h>

// VQ layer forward == identity on inputs (rel_err 1.1e-8 across all rounds,
// gate 1e-3): quantized = closest + stop_gradient(inputs - closest) == inputs.
// Optimal kernel = 8 MiB device copy.
//
// Measured floor model (R1-R5): T_kernel ~= T_ovh(~5000 cyc launch ramp,
// ~4.2us at replay clocks) + LTS transfer (16.8MB / 6300 B/cyc ~= 1.7us),
// identical across LDG/STG, TMA-bulk, and copy-engine paths. Remaining
// lever: R1's 2048-CTA grid ran 2 occupancy waves (1184 concurrent max),
// exposing part of T_wave_trans (~2360 cyc). This config is single-wave
// with the same total outstanding-load count:
//   1024 CTAs x 256 thr x 2 front-batched float4 = 524,288 vectors exactly.

__global__ void vq_copy_sw2(const float4* __restrict__ src,
                            float4* __restrict__ dst,
                            int n4) {
    const int nthreads = gridDim.x * blockDim.x;     // 262,144
    int i0 = blockIdx.x * blockDim.x + threadIdx.x;
    int i1 = i0 + nthreads;

    if (i1 < n4) {
        // Front-batched: both loads in flight before either store (MLP=2).
        float4 v0 = src[i0];
        float4 v1 = src[i1];
        dst[i0] = v0;
        dst[i1] = v1;
    } else {
        for (int j = i0; j < n4; j += nthreads) dst[j] = src[j];
    }
}

extern "C" void kernel_launch(void* const* d_in, const int* in_sizes, int n_in,
                              void* d_out, int out_size) {
    const float* inputs = (const float*)d_in[0];
    float* out = (float*)d_out;

    int n4 = out_size >> 2;                       // 524,288 float4
    const int threads = 256;
    const int vec = 2;
    int blocks = (n4 + threads * vec - 1) / (threads * vec);  // 1024 -> 1 wave

    vq_copy_sw2<<<blocks, threads>>>((const float4*)inputs, (float4*)out, n4);
}